// round 9
// baseline (speedup 1.0000x reference)
#include <cuda_runtime.h>
#include <cuda_fp16.h>
#include <math.h>
#include <stdint.h>

#define NROWS   131072
#define DDIM    64
#define KCODES  512
#define QSIZE   8388608
#define ENCSIZE 67108864
#define ENC_OFF (QSIZE + 1)
#define PERP_OFF (QSIZE + 1 + ENCSIZE)

#define ROWS_PB 128
#define NT      128
#define CAP     40            // per-row candidate cap
#define WT_STR  516           // u32 stride of Wt rows in smem (2064B, 16B-mult)

// dynamic smem layout (bytes)
#define OFF_WT   0                        // u32 Wt[32][516]: half2 (w[k][2ip],w[k][2ip+1]) 66048
#define OFF_W2   66048                    // f32 w2s[512]                                    2048
#define OFF_H    68096                    // int hist[512]                                   2048
#define OFF_CND  70144                    // int cnd[128][CAP]                              20480
#define SMEM_BYTES 90624

__device__ int      g_idx[NROWS];
__device__ int      g_counts[KCODES];
__device__ double   g_loss;
__device__ float    g_w2[KCODES];
__device__ float    g_wmax;              // max element |w|
__device__ uint32_t g_wh[32 * KCODES];   // half2-packed codebook, [ip][k]

// Prep: w2[k] = sum_i round(w[k][i]^2) sequential non-fused (mimics
// jnp.sum(w*w,axis=1)); zero counters; global max|w|; half2-packed codebook.
__global__ void w2_kernel(const float* __restrict__ w) {
    __shared__ float redm[KCODES];
    int k = threadIdx.x;
    float s = 0.0f, amax = 0.0f;
    float wr[DDIM];
    #pragma unroll 8
    for (int i = 0; i < DDIM; ++i) {
        float v = w[k * DDIM + i];
        wr[i] = v;
        s = __fadd_rn(s, __fmul_rn(v, v));
        amax = fmaxf(amax, fabsf(v));
    }
    g_w2[k] = s;
    g_counts[k] = 0;
    if (k == 0) g_loss = 0.0;
    redm[k] = amax;
    // pack half2 pairs: g_wh[ip*512 + k] = (h(w[k][2ip]), h(w[k][2ip+1]))
    #pragma unroll
    for (int ip = 0; ip < 32; ++ip) {
        __half2 p = __floats2half2_rn(wr[2 * ip], wr[2 * ip + 1]);
        g_wh[ip * KCODES + k] = *(uint32_t*)&p;
    }
    __syncthreads();
    for (int st = 256; st; st >>= 1) {
        if (k < st) redm[k] = fmaxf(redm[k], redm[k + st]);
        __syncthreads();
    }
    if (k == 0) g_wmax = redm[0];
}

// Main: HFMA2 (2 MAC/issue) approximate scores with a runtime-sound margin ->
// candidate filter -> exact fp32 sequential refinement (reference rounding +
// first-index ties) -> quantized out, loss, histogram, streamed enc zero-fill.
__global__ __launch_bounds__(NT, 2)
void main_kernel(const float* __restrict__ x, const float* __restrict__ w,
                 float* __restrict__ out) {
    extern __shared__ char sm[];
    uint32_t* Wt  = (uint32_t*)(sm + OFF_WT);
    float*    w2s = (float*)(sm + OFF_W2);
    int*      hist= (int*)(sm + OFF_H);
    int*      cnd = (int*)(sm + OFF_CND);

    int tid  = threadIdx.x;
    int lane = tid & 31;
    int wid  = tid >> 5;

    int row0 = blockIdx.x * ROWS_PB;
    int b    = row0 >> 12;
    int hw0  = row0 & 4095;
    const size_t xbase = (size_t)b * 262144 + hw0;

    // ---- load own row, compute S (sequential NON-fused, matches reference),
    //      pack fp16 pairs; f is then dead until after the scan ----
    float S = 0.0f, rmax = 0.0f;
    __half2 fh[32];
    {
        float f[DDIM];
        #pragma unroll
        for (int c = 0; c < DDIM; ++c) f[c] = x[xbase + (size_t)c * 4096 + tid];
        #pragma unroll
        for (int c = 0; c < DDIM; ++c) S = __fadd_rn(S, __fmul_rn(f[c], f[c]));
        #pragma unroll
        for (int c = 0; c < DDIM; ++c) rmax = fmaxf(rmax, fabsf(f[c]));
        #pragma unroll
        for (int ip = 0; ip < 32; ++ip)
            fh[ip] = __floats2half2_rn(f[2 * ip], f[2 * ip + 1]);
    }

    // ---- stage packed codebook + w2 into smem ----
    for (int idx = tid; idx < 32 * KCODES; idx += NT) {
        int ip = idx >> 9, k = idx & 511;
        Wt[ip * WT_STR + k] = g_wh[idx];
    }
    for (int i = tid; i < KCODES; i += NT) { w2s[i] = g_w2[i]; hist[i] = 0; }
    __syncthreads();

    // ---- sound margin: fp16 seq-accum err (Sum_j bound) + input quant ----
    //   errdot <= eps16*rmax*wmax*(2*528 + 128)*1.01 + subnormal floor
    float margin = 1.25f * rmax * g_wmax + 3e-5f;

    float runmin = __int_as_float(0x7f800000);
    int   cnt = 0;
    int*  mylist = cnd + tid * CAP;

    // ---- scan: 16 codes per group, 32 packed i-steps, broadcast LDS ----
    for (int g = 0; g < KCODES; g += 16) {
        __half2 acc[16];
        #pragma unroll
        for (int j = 0; j < 16; ++j) acc[j] = __floats2half2_rn(0.f, 0.f);
        #pragma unroll
        for (int ip = 0; ip < 32; ++ip) {
            const uint32_t* wp = Wt + ip * WT_STR + g;
            uint4 wa = *(const uint4*)wp;
            uint4 wb = *(const uint4*)(wp + 4);
            uint4 wc = *(const uint4*)(wp + 8);
            uint4 wd = *(const uint4*)(wp + 12);
            acc[0]  = __hfma2(fh[ip], *(__half2*)&wa.x, acc[0]);
            acc[1]  = __hfma2(fh[ip], *(__half2*)&wa.y, acc[1]);
            acc[2]  = __hfma2(fh[ip], *(__half2*)&wa.z, acc[2]);
            acc[3]  = __hfma2(fh[ip], *(__half2*)&wa.w, acc[3]);
            acc[4]  = __hfma2(fh[ip], *(__half2*)&wb.x, acc[4]);
            acc[5]  = __hfma2(fh[ip], *(__half2*)&wb.y, acc[5]);
            acc[6]  = __hfma2(fh[ip], *(__half2*)&wb.z, acc[6]);
            acc[7]  = __hfma2(fh[ip], *(__half2*)&wb.w, acc[7]);
            acc[8]  = __hfma2(fh[ip], *(__half2*)&wc.x, acc[8]);
            acc[9]  = __hfma2(fh[ip], *(__half2*)&wc.y, acc[9]);
            acc[10] = __hfma2(fh[ip], *(__half2*)&wc.z, acc[10]);
            acc[11] = __hfma2(fh[ip], *(__half2*)&wc.w, acc[11]);
            acc[12] = __hfma2(fh[ip], *(__half2*)&wd.x, acc[12]);
            acc[13] = __hfma2(fh[ip], *(__half2*)&wd.y, acc[13]);
            acc[14] = __hfma2(fh[ip], *(__half2*)&wd.z, acc[14]);
            acc[15] = __hfma2(fh[ip], *(__half2*)&wd.w, acc[15]);
        }
        #pragma unroll
        for (int j = 0; j < 16; ++j) {
            float2 lh = __half22float2(acc[j]);
            float dot = lh.x + lh.y;
            float s   = fmaf(-2.0f, dot, w2s[g + j]);
            if (s <= runmin + margin) { if (cnt < CAP) mylist[cnt] = g + j; cnt++; }
            runmin = fminf(runmin, s);
        }
    }

    // ---- streamed enc zero-fill (hidden under compute) ----
    {
        float* enc = out + ENC_OFF;
        int wrow0 = row0 + wid * 32;
        float4 z = make_float4(0.f, 0.f, 0.f, 0.f);
        for (int rr = 0; rr < 32; ++rr) {
            float* eb = enc + (size_t)(wrow0 + rr) * KCODES;
            float4* v4 = (float4*)(eb + 3);          // 16B aligned
            #pragma unroll
            for (int it = 0; it < 4; ++it) {
                int j = lane + 32 * it;
                if (j < 127) __stcs(&v4[j], z);
            }
            if (lane < 3) __stcs(&eb[lane], 0.f);
            if (lane == 3) __stcs(&eb[511], 0.f);
        }
    }

    // ---- reload f (identical bits) for exact refinement + outputs ----
    float f[DDIM];
    #pragma unroll
    for (int c = 0; c < DDIM; ++c) f[c] = x[xbase + (size_t)c * 4096 + tid];

    // ---- exact refinement (reference-identical rounding, first-index ties) ----
    float db = __int_as_float(0x7f800000);
    int   kb = 0;
    if (cnt <= CAP) {
        for (int j = 0; j < cnt; ++j) {
            int k = mylist[j];                       // ascending k order
            const float4* wr = (const float4*)(w + (size_t)k * DDIM);
            float a = 0.0f;
            #pragma unroll
            for (int q = 0; q < 16; ++q) {           // i-order 0..63 sequential
                float4 t = __ldg(&wr[q]);
                a = fmaf(f[4 * q + 0], t.x, a);
                a = fmaf(f[4 * q + 1], t.y, a);
                a = fmaf(f[4 * q + 2], t.z, a);
                a = fmaf(f[4 * q + 3], t.w, a);
            }
            float dd = fmaf(-2.0f, a, __fadd_rn(S, w2s[k]));
            if (dd < db) { db = dd; kb = k; }
        }
    } else {                                         // overflow: full exact scan
        for (int k = 0; k < KCODES; ++k) {
            const float4* wr = (const float4*)(w + (size_t)k * DDIM);
            float a = 0.0f;
            #pragma unroll
            for (int q = 0; q < 16; ++q) {
                float4 t = __ldg(&wr[q]);
                a = fmaf(f[4 * q + 0], t.x, a);
                a = fmaf(f[4 * q + 1], t.y, a);
                a = fmaf(f[4 * q + 2], t.z, a);
                a = fmaf(f[4 * q + 3], t.w, a);
            }
            float dd = fmaf(-2.0f, a, __fadd_rn(S, w2s[k]));
            if (dd < db) { db = dd; kb = k; }
        }
    }

    g_idx[row0 + tid] = kb;
    atomicAdd(&hist[kb], 1);

    // ---- quantized output + loss partials (reference rounding) ----
    const float* wbr = w + (size_t)kb * DDIM;
    float* outp = out + xbase;
    float lsum = 0.0f;
    #pragma unroll
    for (int c = 0; c < DDIM; ++c) {
        float q  = wbr[c];
        float dd = __fsub_rn(q, f[c]);
        outp[(size_t)c * 4096 + tid] = __fadd_rn(f[c], dd);
        lsum = fmaf(dd, dd, lsum);
    }
    #pragma unroll
    for (int o = 16; o; o >>= 1) lsum += __shfl_down_sync(0xffffffffu, lsum, o);
    if (lane == 0) atomicAdd(&g_loss, (double)lsum);

    __syncthreads();
    for (int i = tid; i < KCODES; i += NT)
        if (hist[i]) atomicAdd(&g_counts[i], hist[i]);
}

__global__ void ones_kernel(float* __restrict__ enc) {
    int n = blockIdx.x * 256 + threadIdx.x;
    enc[(size_t)n * KCODES + g_idx[n]] = 1.0f;
}

__global__ void final_kernel(float* __restrict__ out) {
    __shared__ double red[KCODES];
    int t = threadIdx.x;
    float p = (float)g_counts[t] * (1.0f / 131072.0f);
    float term = __fmul_rn(p, logf(__fadd_rn(p, 1e-10f)));
    red[t] = (double)term;
    __syncthreads();
    for (int s = 256; s; s >>= 1) {
        if (t < s) red[t] += red[t + s];
        __syncthreads();
    }
    if (t == 0) {
        out[PERP_OFF] = expf(-(float)red[0]);
        float m = (float)(g_loss / (double)QSIZE);
        out[QSIZE] = __fadd_rn(m, __fmul_rn(0.25f, m));
    }
}

extern "C" void kernel_launch(void* const* d_in, const int* in_sizes, int n_in,
                              void* d_out, int out_size) {
    const float* x = (const float*)d_in[0];
    const float* w = (const float*)d_in[1];
    float* out = (float*)d_out;

    cudaFuncSetAttribute(main_kernel, cudaFuncAttributeMaxDynamicSharedMemorySize,
                         SMEM_BYTES);

    w2_kernel<<<1, KCODES>>>(w);
    main_kernel<<<NROWS / ROWS_PB, NT, SMEM_BYTES>>>(x, w, out);
    ones_kernel<<<NROWS / 256, 256>>>(out + ENC_OFF);
    final_kernel<<<1, KCODES>>>(out);
}

// round 10
// speedup vs baseline: 1.3855x; 1.3855x over previous
#include <cuda_runtime.h>
#include <cuda_fp16.h>
#include <math.h>
#include <stdint.h>

#define NROWS   131072
#define DDIM    64
#define KCODES  512
#define QSIZE   8388608
#define ENCSIZE 67108864
#define ENC_OFF (QSIZE + 1)
#define PERP_OFF (QSIZE + 1 + ENCSIZE)

#define ROWS_PB 128
#define NT      128
#define CAP     40            // per-row candidate cap
#define WT_STR  516           // u32 stride of Wt rows in smem (2064B, 16B-mult)

// dynamic smem layout (bytes)
#define OFF_WT   0                        // u32 Wt[32][516]: half2 (w[k][2ip],w[k][2ip+1]) 66048
#define OFF_W2   66048                    // f32 w2s[512]                                    2048
#define OFF_H    68096                    // int hist[512]                                   2048
#define OFF_CND  70144                    // int cnd[128][CAP]                              20480
#define SMEM_BYTES 90624

__device__ int      g_idx[NROWS];
__device__ int      g_counts[KCODES];
__device__ double   g_loss;
__device__ float    g_w2[KCODES];
__device__ float    g_w2max;             // max_k sum_i w[k][i]^2
__device__ uint32_t g_wh[32 * KCODES];   // half2-packed codebook, [ip][k]

// Prep: w2[k] = sum_i round(w[k][i]^2) sequential non-fused (mimics
// jnp.sum(w*w,axis=1)); zero counters; w2max; half2-packed codebook.
__global__ void w2_kernel(const float* __restrict__ w) {
    __shared__ float redm[KCODES];
    int k = threadIdx.x;
    float s = 0.0f;
    float wr[DDIM];
    #pragma unroll 8
    for (int i = 0; i < DDIM; ++i) {
        float v = w[k * DDIM + i];
        wr[i] = v;
        s = __fadd_rn(s, __fmul_rn(v, v));
    }
    g_w2[k] = s;
    g_counts[k] = 0;
    if (k == 0) g_loss = 0.0;
    redm[k] = s;
    #pragma unroll
    for (int ip = 0; ip < 32; ++ip) {
        __half2 p = __floats2half2_rn(wr[2 * ip], wr[2 * ip + 1]);
        g_wh[ip * KCODES + k] = *(uint32_t*)&p;
    }
    __syncthreads();
    for (int st = 256; st; st >>= 1) {
        if (k < st) redm[k] = fmaxf(redm[k], redm[k + st]);
        __syncthreads();
    }
    if (k == 0) g_w2max = redm[0];
}

// Main: HFMA2 scan (2 short chains per code) with Cauchy-Schwarz-sound margin
// -> candidate filter -> exact fp32 sequential refinement (reference rounding
// + first-index ties) -> quantized out, loss, histogram, enc zero-fill + ones.
__global__ __launch_bounds__(NT, 2)
void main_kernel(const float* __restrict__ x, const float* __restrict__ w,
                 float* __restrict__ out) {
    extern __shared__ char sm[];
    uint32_t* Wt  = (uint32_t*)(sm + OFF_WT);
    float*    w2s = (float*)(sm + OFF_W2);
    int*      hist= (int*)(sm + OFF_H);
    int*      cnd = (int*)(sm + OFF_CND);

    int tid  = threadIdx.x;
    int lane = tid & 31;
    int wid  = tid >> 5;

    int row0 = blockIdx.x * ROWS_PB;
    int b    = row0 >> 12;
    int hw0  = row0 & 4095;
    const size_t xbase = (size_t)b * 262144 + hw0;

    // ---- load own row, compute S (sequential NON-fused, matches reference),
    //      pack fp16 pairs; fp32 f is dead until after the scan ----
    float S = 0.0f;
    __half2 fh[32];
    {
        float f[DDIM];
        #pragma unroll
        for (int c = 0; c < DDIM; ++c) f[c] = x[xbase + (size_t)c * 4096 + tid];
        #pragma unroll
        for (int c = 0; c < DDIM; ++c) S = __fadd_rn(S, __fmul_rn(f[c], f[c]));
        #pragma unroll
        for (int ip = 0; ip < 32; ++ip)
            fh[ip] = __floats2half2_rn(f[2 * ip], f[2 * ip + 1]);
    }

    // ---- stage packed codebook + w2 into smem ----
    for (int idx = tid; idx < 32 * KCODES; idx += NT) {
        int ip = idx >> 9, k = idx & 511;
        Wt[ip * WT_STR + k] = g_wh[idx];
    }
    for (int i = tid; i < KCODES; i += NT) { w2s[i] = g_w2[i]; hist[i] = 0; }
    __syncthreads();

    // ---- sound margin via Cauchy-Schwarz partial-sum bound ----
    // every sub-chain partial |p| <= sum|f_i w_i| <= sqrt(S*w2max);
    // chain len 16 => dot err <= (16 + 2 conv + slack)*2^-11*CS
    float CS = sqrtf(S * g_w2max);
    float margin = 0.025f * CS + 1e-4f;

    float runmin = __int_as_float(0x7f800000);
    int   cnt = 0;
    int*  mylist = cnd + tid * CAP;

    // ---- scan: 8 codes/group, 2 interleaved half2 chains per code ----
    for (int g = 0; g < KCODES; g += 8) {
        __half2 aA[8], aB[8];
        #pragma unroll
        for (int j = 0; j < 8; ++j) {
            aA[j] = __floats2half2_rn(0.f, 0.f);
            aB[j] = __floats2half2_rn(0.f, 0.f);
        }
        #pragma unroll
        for (int ip = 0; ip < 32; ip += 2) {
            const uint32_t* wp0 = Wt + ip * WT_STR + g;
            const uint32_t* wp1 = wp0 + WT_STR;
            uint4 wa = *(const uint4*)wp0;
            uint4 wb = *(const uint4*)(wp0 + 4);
            uint4 wc = *(const uint4*)wp1;
            uint4 wd = *(const uint4*)(wp1 + 4);
            __half2 f0 = fh[ip], f1 = fh[ip + 1];
            aA[0] = __hfma2(f0, *(__half2*)&wa.x, aA[0]);
            aA[1] = __hfma2(f0, *(__half2*)&wa.y, aA[1]);
            aA[2] = __hfma2(f0, *(__half2*)&wa.z, aA[2]);
            aA[3] = __hfma2(f0, *(__half2*)&wa.w, aA[3]);
            aA[4] = __hfma2(f0, *(__half2*)&wb.x, aA[4]);
            aA[5] = __hfma2(f0, *(__half2*)&wb.y, aA[5]);
            aA[6] = __hfma2(f0, *(__half2*)&wb.z, aA[6]);
            aA[7] = __hfma2(f0, *(__half2*)&wb.w, aA[7]);
            aB[0] = __hfma2(f1, *(__half2*)&wc.x, aB[0]);
            aB[1] = __hfma2(f1, *(__half2*)&wc.y, aB[1]);
            aB[2] = __hfma2(f1, *(__half2*)&wc.z, aB[2]);
            aB[3] = __hfma2(f1, *(__half2*)&wc.w, aB[3]);
            aB[4] = __hfma2(f1, *(__half2*)&wd.x, aB[4]);
            aB[5] = __hfma2(f1, *(__half2*)&wd.y, aB[5]);
            aB[6] = __hfma2(f1, *(__half2*)&wd.z, aB[6]);
            aB[7] = __hfma2(f1, *(__half2*)&wd.w, aB[7]);
        }
        #pragma unroll
        for (int j = 0; j < 8; ++j) {
            float2 u = __half22float2(aA[j]);
            float2 v = __half22float2(aB[j]);
            float dot = (u.x + u.y) + (v.x + v.y);
            float s   = fmaf(-2.0f, dot, w2s[g + j]);
            if (s <= runmin + margin) { if (cnt < CAP) mylist[cnt] = g + j; cnt++; }
            runmin = fminf(runmin, s);
        }
    }

    // ---- streamed enc zero-fill (hidden under compute) ----
    {
        float* enc = out + ENC_OFF;
        int wrow0 = row0 + wid * 32;
        float4 z = make_float4(0.f, 0.f, 0.f, 0.f);
        for (int rr = 0; rr < 32; ++rr) {
            float* eb = enc + (size_t)(wrow0 + rr) * KCODES;
            float4* v4 = (float4*)(eb + 3);          // 16B aligned
            #pragma unroll
            for (int it = 0; it < 4; ++it) {
                int j = lane + 32 * it;
                if (j < 127) __stcs(&v4[j], z);
            }
            if (lane < 3) __stcs(&eb[lane], 0.f);
            if (lane == 3) __stcs(&eb[511], 0.f);
        }
    }

    // ---- reload f (identical bits) for exact refinement + outputs ----
    float f[DDIM];
    #pragma unroll
    for (int c = 0; c < DDIM; ++c) f[c] = x[xbase + (size_t)c * 4096 + tid];

    // ---- exact refinement (reference-identical rounding, first-index ties) ----
    float db = __int_as_float(0x7f800000);
    int   kb = 0;
    if (cnt <= CAP) {
        for (int j = 0; j < cnt; ++j) {
            int k = mylist[j];                       // ascending k order
            const float4* wr = (const float4*)(w + (size_t)k * DDIM);
            float a = 0.0f;
            #pragma unroll
            for (int q = 0; q < 16; ++q) {           // i-order 0..63 sequential
                float4 t = __ldg(&wr[q]);
                a = fmaf(f[4 * q + 0], t.x, a);
                a = fmaf(f[4 * q + 1], t.y, a);
                a = fmaf(f[4 * q + 2], t.z, a);
                a = fmaf(f[4 * q + 3], t.w, a);
            }
            float dd = fmaf(-2.0f, a, __fadd_rn(S, w2s[k]));
            if (dd < db) { db = dd; kb = k; }
        }
    } else {                                         // overflow: full exact scan
        for (int k = 0; k < KCODES; ++k) {
            const float4* wr = (const float4*)(w + (size_t)k * DDIM);
            float a = 0.0f;
            #pragma unroll
            for (int q = 0; q < 16; ++q) {
                float4 t = __ldg(&wr[q]);
                a = fmaf(f[4 * q + 0], t.x, a);
                a = fmaf(f[4 * q + 1], t.y, a);
                a = fmaf(f[4 * q + 2], t.z, a);
                a = fmaf(f[4 * q + 3], t.w, a);
            }
            float dd = fmaf(-2.0f, a, __fadd_rn(S, w2s[k]));
            if (dd < db) { db = dd; kb = k; }
        }
    }

    g_idx[row0 + tid] = kb;
    atomicAdd(&hist[kb], 1);

    __syncthreads();   // orders the 1-write after this block's zero-fill

    // ---- one-hot 1-write (fused; row owned by this thread) ----
    out[ENC_OFF + (size_t)(row0 + tid) * KCODES + kb] = 1.0f;

    // ---- quantized output + loss partials (reference rounding) ----
    const float* wbr = w + (size_t)kb * DDIM;
    float* outp = out + xbase;
    float lsum = 0.0f;
    #pragma unroll
    for (int c = 0; c < DDIM; ++c) {
        float q  = wbr[c];
        float dd = __fsub_rn(q, f[c]);
        outp[(size_t)c * 4096 + tid] = __fadd_rn(f[c], dd);
        lsum = fmaf(dd, dd, lsum);
    }
    #pragma unroll
    for (int o = 16; o; o >>= 1) lsum += __shfl_down_sync(0xffffffffu, lsum, o);
    if (lane == 0) atomicAdd(&g_loss, (double)lsum);

    for (int i = tid; i < KCODES; i += NT)
        if (hist[i]) atomicAdd(&g_counts[i], hist[i]);
}

__global__ void final_kernel(float* __restrict__ out) {
    __shared__ double red[KCODES];
    int t = threadIdx.x;
    float p = (float)g_counts[t] * (1.0f / 131072.0f);
    float term = __fmul_rn(p, logf(__fadd_rn(p, 1e-10f)));
    red[t] = (double)term;
    __syncthreads();
    for (int s = 256; s; s >>= 1) {
        if (t < s) red[t] += red[t + s];
        __syncthreads();
    }
    if (t == 0) {
        out[PERP_OFF] = expf(-(float)red[0]);
        float m = (float)(g_loss / (double)QSIZE);
        out[QSIZE] = __fadd_rn(m, __fmul_rn(0.25f, m));
    }
}

extern "C" void kernel_launch(void* const* d_in, const int* in_sizes, int n_in,
                              void* d_out, int out_size) {
    const float* x = (const float*)d_in[0];
    const float* w = (const float*)d_in[1];
    float* out = (float*)d_out;

    cudaFuncSetAttribute(main_kernel, cudaFuncAttributeMaxDynamicSharedMemorySize,
                         SMEM_BYTES);

    w2_kernel<<<1, KCODES>>>(w);
    main_kernel<<<NROWS / ROWS_PB, NT, SMEM_BYTES>>>(x, w, out);
    final_kernel<<<1, KCODES>>>(out);
}

// round 11
// speedup vs baseline: 1.4874x; 1.0736x over previous
#include <cuda_runtime.h>
#include <cuda_fp16.h>
#include <math.h>
#include <stdint.h>

#define NROWS   131072
#define DDIM    64
#define KCODES  512
#define QSIZE   8388608
#define ENCSIZE 67108864
#define ENC_OFF (QSIZE + 1)
#define PERP_OFF (QSIZE + 1 + ENCSIZE)

#define ROWS_PB 128
#define NT      128
#define CAP     32            // per-row candidate cap (appends incl. prefix-min noise)
#define WT_STR  516           // u32 stride of Wt rows in smem (2064B, 16B-mult)

// dynamic smem layout (bytes)
#define OFF_WT   0                        // u32 Wt[32][516]: half2 (w[k][2ip],w[k][2ip+1]) 66048
#define OFF_W2   66048                    // f32 w2s[512]                                    2048
#define OFF_H    68096                    // int hist[512]                                   2048
#define OFF_CND  70144                    // int cnd[128][CAP]                              16384
#define OFF_CVS  86528                    // f32 cvs[128][CAP]                              16384
#define SMEM_BYTES 102912

__device__ int      g_idx[NROWS];
__device__ int      g_counts[KCODES];
__device__ double   g_loss;
__device__ float    g_w2[KCODES];
__device__ unsigned g_w2max_bits;        // max_k w2[k], positive-float bits (atomicMax)
__device__ uint32_t g_wh[32 * KCODES];   // half2-packed codebook, [ip][k]

// Prep (4 blocks x 128): coalesced smem staging; w2[k] sequential non-fused
// (mimics jnp.sum(w*w,axis=1)); half2 pack; w2max via atomicMax; zero counters.
__global__ void w2_kernel(const float* __restrict__ w) {
    __shared__ float ws[128][65];
    __shared__ float redm[128];
    int tid = threadIdx.x;
    int kc0 = blockIdx.x * 128;
    for (int idx = tid; idx < 128 * 64; idx += 128) {
        int row = idx >> 6, col = idx & 63;
        ws[row][col] = w[(kc0 + row) * 64 + col];      // coalesced
    }
    g_counts[kc0 + tid] = 0;
    g_counts[kc0 + tid + ((blockIdx.x & 1) ? -128 : 128)] = 0;  // covered anyway below
    __syncthreads();

    int k = kc0 + tid;
    float s = 0.0f;
    #pragma unroll 8
    for (int i = 0; i < DDIM; ++i)
        s = __fadd_rn(s, __fmul_rn(ws[tid][i], ws[tid][i]));
    g_w2[k] = s;
    g_counts[k] = 0;
    if (blockIdx.x == 0 && tid == 0) g_loss = 0.0;
    #pragma unroll
    for (int ip = 0; ip < 32; ++ip) {
        __half2 p = __floats2half2_rn(ws[tid][2 * ip], ws[tid][2 * ip + 1]);
        g_wh[ip * KCODES + k] = *(uint32_t*)&p;
    }
    redm[tid] = s;
    __syncthreads();
    for (int st = 64; st; st >>= 1) {
        if (tid < st) redm[tid] = fmaxf(redm[tid], redm[tid + st]);
        __syncthreads();
    }
    if (tid == 0) atomicMax(&g_w2max_bits, __float_as_uint(redm[0]));  // idempotent
}

// Main: HFMA2 scan (4 len-8 chains/code) with CS-sound margin -> candidate
// append with stored scores -> post-filter vs FINAL min -> exact fp32
// sequential refinement (reference rounding + first-index ties) -> outputs.
__global__ __launch_bounds__(NT, 2)
void main_kernel(const float* __restrict__ x, const float* __restrict__ w,
                 float* __restrict__ out) {
    extern __shared__ char sm[];
    uint32_t* Wt  = (uint32_t*)(sm + OFF_WT);
    float*    w2s = (float*)(sm + OFF_W2);
    int*      hist= (int*)(sm + OFF_H);
    int*      cnd = (int*)(sm + OFF_CND);
    float*    cvs = (float*)(sm + OFF_CVS);

    int tid  = threadIdx.x;
    int lane = tid & 31;
    int wid  = tid >> 5;

    int row0 = blockIdx.x * ROWS_PB;
    int b    = row0 >> 12;
    int hw0  = row0 & 4095;
    const size_t xbase = (size_t)b * 262144 + hw0;

    // ---- load own row, S (sequential NON-fused, matches reference), fp16 pack ----
    float S = 0.0f;
    __half2 fh[32];
    {
        float f[DDIM];
        #pragma unroll
        for (int c = 0; c < DDIM; ++c) f[c] = x[xbase + (size_t)c * 4096 + tid];
        #pragma unroll
        for (int c = 0; c < DDIM; ++c) S = __fadd_rn(S, __fmul_rn(f[c], f[c]));
        #pragma unroll
        for (int ip = 0; ip < 32; ++ip)
            fh[ip] = __floats2half2_rn(f[2 * ip], f[2 * ip + 1]);
    }

    // ---- stage packed codebook + w2 into smem ----
    for (int idx = tid; idx < 32 * KCODES; idx += NT) {
        int ip = idx >> 9, k = idx & 511;
        Wt[ip * WT_STR + k] = g_wh[idx];
    }
    for (int i = tid; i < KCODES; i += NT) { w2s[i] = g_w2[i]; hist[i] = 0; }
    __syncthreads();

    // ---- sound margin: 4 chains of len 8; every partial |.| <= CS ----
    // dot err <= (8 chain + 2 conv)*2^-11*CS  -> score margin = 2x + floor
    float CS = sqrtf(S * __uint_as_float(g_w2max_bits));
    float margin = 0.014f * CS + 1e-4f;

    float runmin = __int_as_float(0x7f800000);
    int   cnt = 0;
    int*   mylist = cnd + tid * CAP;
    float* myvals = cvs + tid * CAP;

    // ---- scan: 8 codes/group, 4 interleaved half2 chains per code ----
    for (int g = 0; g < KCODES; g += 8) {
        __half2 aA[8], aB[8], aC[8], aD[8];
        #pragma unroll
        for (int j = 0; j < 8; ++j) {
            aA[j] = __floats2half2_rn(0.f, 0.f);
            aB[j] = __floats2half2_rn(0.f, 0.f);
            aC[j] = __floats2half2_rn(0.f, 0.f);
            aD[j] = __floats2half2_rn(0.f, 0.f);
        }
        #pragma unroll
        for (int ip = 0; ip < 32; ip += 4) {
            const uint32_t* wp0 = Wt + ip * WT_STR + g;
            const uint32_t* wp1 = wp0 + WT_STR;
            const uint32_t* wp2 = wp1 + WT_STR;
            const uint32_t* wp3 = wp2 + WT_STR;
            uint4 w0a = *(const uint4*)wp0, w0b = *(const uint4*)(wp0 + 4);
            uint4 w1a = *(const uint4*)wp1, w1b = *(const uint4*)(wp1 + 4);
            uint4 w2a = *(const uint4*)wp2, w2b = *(const uint4*)(wp2 + 4);
            uint4 w3a = *(const uint4*)wp3, w3b = *(const uint4*)(wp3 + 4);
            __half2 f0 = fh[ip], f1 = fh[ip + 1], f2 = fh[ip + 2], f3 = fh[ip + 3];
            aA[0] = __hfma2(f0, *(__half2*)&w0a.x, aA[0]);
            aA[1] = __hfma2(f0, *(__half2*)&w0a.y, aA[1]);
            aA[2] = __hfma2(f0, *(__half2*)&w0a.z, aA[2]);
            aA[3] = __hfma2(f0, *(__half2*)&w0a.w, aA[3]);
            aA[4] = __hfma2(f0, *(__half2*)&w0b.x, aA[4]);
            aA[5] = __hfma2(f0, *(__half2*)&w0b.y, aA[5]);
            aA[6] = __hfma2(f0, *(__half2*)&w0b.z, aA[6]);
            aA[7] = __hfma2(f0, *(__half2*)&w0b.w, aA[7]);
            aB[0] = __hfma2(f1, *(__half2*)&w1a.x, aB[0]);
            aB[1] = __hfma2(f1, *(__half2*)&w1a.y, aB[1]);
            aB[2] = __hfma2(f1, *(__half2*)&w1a.z, aB[2]);
            aB[3] = __hfma2(f1, *(__half2*)&w1a.w, aB[3]);
            aB[4] = __hfma2(f1, *(__half2*)&w1b.x, aB[4]);
            aB[5] = __hfma2(f1, *(__half2*)&w1b.y, aB[5]);
            aB[6] = __hfma2(f1, *(__half2*)&w1b.z, aB[6]);
            aB[7] = __hfma2(f1, *(__half2*)&w1b.w, aB[7]);
            aC[0] = __hfma2(f2, *(__half2*)&w2a.x, aC[0]);
            aC[1] = __hfma2(f2, *(__half2*)&w2a.y, aC[1]);
            aC[2] = __hfma2(f2, *(__half2*)&w2a.z, aC[2]);
            aC[3] = __hfma2(f2, *(__half2*)&w2a.w, aC[3]);
            aC[4] = __hfma2(f2, *(__half2*)&w2b.x, aC[4]);
            aC[5] = __hfma2(f2, *(__half2*)&w2b.y, aC[5]);
            aC[6] = __hfma2(f2, *(__half2*)&w2b.z, aC[6]);
            aC[7] = __hfma2(f2, *(__half2*)&w2b.w, aC[7]);
            aD[0] = __hfma2(f3, *(__half2*)&w3a.x, aD[0]);
            aD[1] = __hfma2(f3, *(__half2*)&w3a.y, aD[1]);
            aD[2] = __hfma2(f3, *(__half2*)&w3a.z, aD[2]);
            aD[3] = __hfma2(f3, *(__half2*)&w3a.w, aD[3]);
            aD[4] = __hfma2(f3, *(__half2*)&w3b.x, aD[4]);
            aD[5] = __hfma2(f3, *(__half2*)&w3b.y, aD[5]);
            aD[6] = __hfma2(f3, *(__half2*)&w3b.z, aD[6]);
            aD[7] = __hfma2(f3, *(__half2*)&w3b.w, aD[7]);
        }
        #pragma unroll
        for (int j = 0; j < 8; ++j) {
            float2 u = __half22float2(aA[j]);
            float2 v = __half22float2(aB[j]);
            float2 p = __half22float2(aC[j]);
            float2 q = __half22float2(aD[j]);
            float dot = ((u.x + u.y) + (v.x + v.y)) + ((p.x + p.y) + (q.x + q.y));
            float s   = fmaf(-2.0f, dot, w2s[g + j]);
            if (s <= runmin + margin) {
                if (cnt < CAP) { mylist[cnt] = g + j; myvals[cnt] = s; }
                cnt++;
            }
            runmin = fminf(runmin, s);
        }
    }

    // ---- streamed enc zero-fill (hidden under compute) ----
    {
        float* enc = out + ENC_OFF;
        int wrow0 = row0 + wid * 32;
        float4 z = make_float4(0.f, 0.f, 0.f, 0.f);
        for (int rr = 0; rr < 32; ++rr) {
            float* eb = enc + (size_t)(wrow0 + rr) * KCODES;
            float4* v4 = (float4*)(eb + 3);          // 16B aligned
            #pragma unroll
            for (int it = 0; it < 4; ++it) {
                int j = lane + 32 * it;
                if (j < 127) __stcs(&v4[j], z);
            }
            if (lane < 3) __stcs(&eb[lane], 0.f);
            if (lane == 3) __stcs(&eb[511], 0.f);
        }
    }

    // ---- reload f (identical bits) for exact refinement + outputs ----
    float f[DDIM];
    #pragma unroll
    for (int c = 0; c < DDIM; ++c) f[c] = x[xbase + (size_t)c * 4096 + tid];

    // ---- post-filter vs FINAL min, then exact refinement
    //      (reference-identical rounding, first-index ties) ----
    float thr = runmin + margin;
    float db = __int_as_float(0x7f800000);
    int   kb = 0;
    if (cnt <= CAP) {
        for (int j = 0; j < cnt; ++j) {
            if (myvals[j] > thr) continue;           // drop prefix-min noise
            int k = mylist[j];                       // ascending k order
            const float4* wr = (const float4*)(w + (size_t)k * DDIM);
            float a = 0.0f;
            #pragma unroll
            for (int q = 0; q < 16; ++q) {           // i-order 0..63 sequential
                float4 t = __ldg(&wr[q]);
                a = fmaf(f[4 * q + 0], t.x, a);
                a = fmaf(f[4 * q + 1], t.y, a);
                a = fmaf(f[4 * q + 2], t.z, a);
                a = fmaf(f[4 * q + 3], t.w, a);
            }
            float dd = fmaf(-2.0f, a, __fadd_rn(S, w2s[k]));
            if (dd < db) { db = dd; kb = k; }
        }
    } else {                                         // overflow: full exact scan
        for (int k = 0; k < KCODES; ++k) {
            const float4* wr = (const float4*)(w + (size_t)k * DDIM);
            float a = 0.0f;
            #pragma unroll
            for (int q = 0; q < 16; ++q) {
                float4 t = __ldg(&wr[q]);
                a = fmaf(f[4 * q + 0], t.x, a);
                a = fmaf(f[4 * q + 1], t.y, a);
                a = fmaf(f[4 * q + 2], t.z, a);
                a = fmaf(f[4 * q + 3], t.w, a);
            }
            float dd = fmaf(-2.0f, a, __fadd_rn(S, w2s[k]));
            if (dd < db) { db = dd; kb = k; }
        }
    }

    g_idx[row0 + tid] = kb;
    atomicAdd(&hist[kb], 1);

    __syncthreads();   // orders the 1-write after this block's zero-fill

    // ---- one-hot 1-write (fused) ----
    out[ENC_OFF + (size_t)(row0 + tid) * KCODES + kb] = 1.0f;

    // ---- quantized output + loss partials (reference rounding) ----
    const float* wbr = w + (size_t)kb * DDIM;
    float* outp = out + xbase;
    float lsum = 0.0f;
    #pragma unroll
    for (int c = 0; c < DDIM; ++c) {
        float q  = wbr[c];
        float dd = __fsub_rn(q, f[c]);
        outp[(size_t)c * 4096 + tid] = __fadd_rn(f[c], dd);
        lsum = fmaf(dd, dd, lsum);
    }
    #pragma unroll
    for (int o = 16; o; o >>= 1) lsum += __shfl_down_sync(0xffffffffu, lsum, o);
    if (lane == 0) atomicAdd(&g_loss, (double)lsum);

    for (int i = tid; i < KCODES; i += NT)
        if (hist[i]) atomicAdd(&g_counts[i], hist[i]);
}

__global__ void final_kernel(float* __restrict__ out) {
    __shared__ double red[KCODES];
    int t = threadIdx.x;
    float p = (float)g_counts[t] * (1.0f / 131072.0f);
    float term = __fmul_rn(p, logf(__fadd_rn(p, 1e-10f)));
    red[t] = (double)term;
    __syncthreads();
    for (int s = 256; s; s >>= 1) {
        if (t < s) red[t] += red[t + s];
        __syncthreads();
    }
    if (t == 0) {
        out[PERP_OFF] = expf(-(float)red[0]);
        float m = (float)(g_loss / (double)QSIZE);
        out[QSIZE] = __fadd_rn(m, __fmul_rn(0.25f, m));
    }
}

extern "C" void kernel_launch(void* const* d_in, const int* in_sizes, int n_in,
                              void* d_out, int out_size) {
    const float* x = (const float*)d_in[0];
    const float* w = (const float*)d_in[1];
    float* out = (float*)d_out;

    cudaFuncSetAttribute(main_kernel, cudaFuncAttributeMaxDynamicSharedMemorySize,
                         SMEM_BYTES);

    w2_kernel<<<4, 128>>>(w);
    main_kernel<<<NROWS / ROWS_PB, NT, SMEM_BYTES>>>(x, w, out);
    final_kernel<<<1, KCODES>>>(out);
}